// round 10
// baseline (speedup 1.0000x reference)
#include <cuda_runtime.h>

// ReduceBoundingBoxes, SINGLE kernel, SINGLE block, bucketed counting sort.
// One full-pixel pass only; all later phases run on the compact valid list.
//   S1: prefetch ch0..4 to L2, zero hist, zero out
//   S2: pixel pass: histogram + warp-aggregated append (key -> klist)
//   S3: block prefix-sum over 4096 buckets
//   S4: scatter klist -> scat (bucket-ordered), 1 elem/thread
//   S5: rank (in-bucket compares only on collisions) + gather + write rows
//   S6: warp-0 greedy NMS over non-degenerate boxes (reads boxes from out)
// x: (5, 80, 80) f32 channel-major. out: (6400, 5) f32.
//
// key = (u64(~bits(score)) << 32) | idx ; ascending == (score desc, idx asc).
// Valid scores s in (0.9, 1.0) share exponent 126 -> u = ~bits(s) lies in
// (0xC0800000, 0xC099999A); bucket = clamp((u - 0xC0800000) >> 9, 0, 4095)
// is monotone in u. Out-of-range scores clamp into end buckets, resolved by
// exact u64 compares -> correct for any input.

#define NPIX 6400
#define NT   1024
#define NB   4096

// dynamic smem layout (bytes):
//   [0,      51200)  u64 klist[6400]   (compact valid keys, unordered)
//                    reused as int ndlist[6400] after S4
//   [51200,  67584)  int cursor[4096]  (hist -> running offsets)
//                    reused as u8 kb[6400] after S4
//   [67584,  83976)  int base0[4097] (+pad)
//   [83976, 135176)  u64 scat[6400]    (keys, bucket-ordered)
//   [135176,141576)  u8 ndflag[6400]
#define KLIST_OFF  0
#define CUR_OFF    51200
#define BASE_OFF   67584
#define SCAT_OFF   83976
#define NDFLAG_OFF 135176
#define SMEM_BYTES 141576

__device__ __forceinline__ int bucket_of(unsigned u) {
    unsigned d = u - 0xC0800000u;
    int b = (u < 0xC0800000u) ? 0 : (int)(d >> 9);
    return b > (NB - 1) ? (NB - 1) : b;
}

__global__ void __launch_bounds__(NT, 1)
bb_kernel(const float* __restrict__ x, float* __restrict__ out) {
    extern __shared__ unsigned char smem[];
    unsigned long long* klist  = (unsigned long long*)(smem + KLIST_OFF);
    int*                ndlist = (int*)(smem + KLIST_OFF);  // reuse after S4
    int*                cursor = (int*)(smem + CUR_OFF);
    unsigned char*      kb     = smem + CUR_OFF;            // reuse after S4
    int*                base0  = (int*)(smem + BASE_OFF);
    unsigned long long* scat   = (unsigned long long*)(smem + SCAT_OFF);
    unsigned char*      ndflag = smem + NDFLAG_OFF;
    __shared__ int wsum[32];
    __shared__ int sM;

    const int tid  = threadIdx.x;
    const int lane = tid & 31;
    const int wid  = tid >> 5;

    // ---- S1: prefetch all of x to L2, zero hist, zero out ----
    if (tid < 1000) {   // 128000 B / 128 B = 1000 lines
        const char* p = (const char*)x + tid * 128;
        asm volatile("prefetch.global.L2 [%0];" :: "l"(p));
    }
    #pragma unroll
    for (int i = tid; i < NB; i += NT) cursor[i] = 0;
    float4* o4 = (float4*)out;
    #pragma unroll
    for (int i = tid; i < (NPIX * 5) / 4; i += NT)
        o4[i] = make_float4(0.f, 0.f, 0.f, 0.f);
    if (tid == 0) sM = 0;
    __syncthreads();

    // ---- S2: single pixel pass: histogram + compact key list ----
    #pragma unroll
    for (int it = 0; it < NPIX / NT + 1; it++) {
        int i = tid + it * NT;
        bool v = false;
        unsigned u = 0;
        if (i < NPIX) {
            float s = x[i];                  // channel 0 (prob), L2-warm
            if (s > 0.9f) { v = true; u = ~__float_as_uint(s); }
        }
        if (v) atomicAdd(&cursor[bucket_of(u)], 1);
        unsigned bal = __ballot_sync(0xffffffffu, v);
        if (bal) {
            int leader = __ffs(bal) - 1;
            int base;
            if (lane == leader) base = atomicAdd(&sM, __popc(bal));
            base = __shfl_sync(0xffffffffu, base, leader);
            if (v) {
                int p = base + __popc(bal & ((1u << lane) - 1u));
                klist[p] = (((unsigned long long)u) << 32) | (unsigned)i;
            }
        }
    }
    __syncthreads();
    const int M = sM;

    if (M > 0) {
        // ---- S3: exclusive prefix sum over 4096 buckets (4/thread) ----
        const int t4 = tid * 4;
        int c0 = cursor[t4], c1 = cursor[t4 + 1];
        int c2 = cursor[t4 + 2], c3 = cursor[t4 + 3];
        int local = c0 + c1 + c2 + c3;
        int v = local;
        #pragma unroll
        for (int j = 1; j < 32; j <<= 1) {
            int n = __shfl_up_sync(0xffffffffu, v, j);
            if (lane >= j) v += n;
        }
        if (lane == 31) wsum[wid] = v;
        __syncthreads();
        if (wid == 0) {
            int w = wsum[lane];
            #pragma unroll
            for (int j = 1; j < 32; j <<= 1) {
                int n = __shfl_up_sync(0xffffffffu, w, j);
                if (lane >= j) w += n;
            }
            wsum[lane] = w;
        }
        __syncthreads();
        int ex = v - local + (wid ? wsum[wid - 1] : 0);
        base0[t4]     = ex;
        base0[t4 + 1] = ex + c0;
        base0[t4 + 2] = ex + c0 + c1;
        base0[t4 + 3] = ex + c0 + c1 + c2;
        cursor[t4]     = ex;
        cursor[t4 + 1] = ex + c0;
        cursor[t4 + 2] = ex + c0 + c1;
        cursor[t4 + 3] = ex + c0 + c1 + c2;
        if (tid == 0) base0[NB] = M;
        __syncthreads();

        // ---- S4: scatter compact list into bucket order (1/thread) ----
        for (int k = tid; k < M; k += NT) {
            unsigned long long key = klist[k];
            int b = bucket_of((unsigned)(key >> 32));
            scat[atomicAdd(&cursor[b], 1)] = key;
        }
        __syncthreads();   // klist/cursor dead -> ndlist/kb reuse OK

        // ---- S5: rank + gather + write rows (1/thread) ----
        // b5 = (f0, f1, f0+f2, f1+f3, f4); box = (f1, f0+f2, f1+f3, f4)
        for (int p = tid; p < M; p += NT) {
            unsigned long long key = scat[p];
            unsigned u = (unsigned)(key >> 32);
            int b = bucket_of(u);
            int s0 = base0[b], e0 = base0[b + 1];
            int r = s0;
            if (e0 - s0 > 1)
                for (int q = s0; q < e0; q++) r += (scat[q] < key);

            unsigned i = (unsigned)key;
            float f0 = __uint_as_float(~u);
            float f1 = x[NPIX + i];          // L2-warm (prefetched)
            float f2 = x[2 * NPIX + i];
            float f3 = x[3 * NPIX + i];
            float f4 = x[4 * NPIX + i];
            float cc2 = f0 + f2;
            float cc3 = f1 + f3;
            out[r * 5 + 0] = f0;
            out[r * 5 + 1] = f1;
            out[r * 5 + 2] = cc2;
            out[r * 5 + 3] = cc3;
            out[r * 5 + 4] = f4;
            ndflag[r] = ((cc3 - f1) > 0.f && (f4 - cc2) > 0.f) ? 1 : 0;
        }
        __syncthreads();

        // ---- S6: warp 0 — greedy NMS over non-degenerate boxes ----
        // degenerate boxes (w<=0 or h<=0) have IoU 0 with everything:
        // never suppressed, never suppress -> rows stay as written.
        if (tid < 32) {
            int g = 0;
            for (int base = 0; base < M; base += 32) {
                int r = base + lane;
                bool f = (r < M) && (ndflag[r] != 0);
                unsigned bal = __ballot_sync(0xffffffffu, f);
                if (f) ndlist[g + __popc(bal & ((1u << lane) - 1u))] = r;
                g += __popc(bal);
            }
            for (int i2 = 0; i2 < g; i2++) {
                int ri = ndlist[i2];
                float ax0 = out[ri * 5 + 1], ay0 = out[ri * 5 + 2];
                float ax1 = out[ri * 5 + 3], ay1 = out[ri * 5 + 4];
                float aarea = fmaxf(ax1 - ax0, 0.f) * fmaxf(ay1 - ay0, 0.f);
                bool sup = false;
                for (int j = lane; j < i2; j += 32) {
                    if (kb[j]) {
                        int rj = ndlist[j];
                        float bx0 = out[rj * 5 + 1], by0 = out[rj * 5 + 2];
                        float bx1 = out[rj * 5 + 3], by1 = out[rj * 5 + 4];
                        float barea = fmaxf(bx1 - bx0, 0.f) *
                                      fmaxf(by1 - by0, 0.f);
                        float iw = fminf(ax1, bx1) - fmaxf(ax0, bx0);
                        float ih = fminf(ay1, by1) - fmaxf(ay0, by0);
                        float inter = fmaxf(iw, 0.f) * fmaxf(ih, 0.f);
                        float uni = aarea + barea - inter;
                        if (inter / fmaxf(uni, 1e-9f) > 0.5f) sup = true;
                    }
                }
                sup = __any_sync(0xffffffffu, sup);
                if (lane == 0) {
                    kb[i2] = sup ? 0 : 1;
                    if (sup) {   // suppressed row -> zeros
                        out[ri * 5 + 0] = 0.f;
                        out[ri * 5 + 1] = 0.f;
                        out[ri * 5 + 2] = 0.f;
                        out[ri * 5 + 3] = 0.f;
                        out[ri * 5 + 4] = 0.f;
                    }
                }
                __syncwarp();
            }
        }
    }
}

extern "C" void kernel_launch(void* const* d_in, const int* in_sizes, int n_in,
                              void* d_out, int out_size) {
    const float* x = (const float*)d_in[0];
    float* out = (float*)d_out;
    cudaFuncSetAttribute(bb_kernel,
                         cudaFuncAttributeMaxDynamicSharedMemorySize,
                         SMEM_BYTES);
    bb_kernel<<<1, NT, SMEM_BYTES>>>(x, out);
}

// round 11
// speedup vs baseline: 1.1629x; 1.1629x over previous
#include <cuda_runtime.h>

// ReduceBoundingBoxes, SINGLE kernel, SINGLE block, bucketed counting sort
// (R7 skeleton: hist pass + scatter pass; M from prefix, no serial atomics).
//   S1: prefetch ALL of x to L2, zero hist, zero out
//   S2: histogram of valid scores (ch0, L2-warm)
//   S3: block prefix-sum over 4096 buckets (int4-vectorized)
//   S4: scatter pass (ch0 reload is L1-hot; smem small enough to keep it)
//   S5: rank (in-bucket compares only on collisions) + gather + write rows
//   S6: parallel order-preserving non-degenerate list build + warp-0 NMS
// x: (5, 80, 80) f32 channel-major. out: (6400, 5) f32.
//
// key = (u64(~bits(score)) << 32) | idx ; ascending == (score desc, idx asc).
// Valid scores s in (0.9, 1.0) share exponent 126 -> u = ~bits(s) lies in
// (0xC0800000, 0xC099999A); bucket = clamp((u - 0xC0800000) >> 9, 0, 4095)
// is monotone in u. Out-of-range scores clamp into end buckets, resolved by
// exact u64 compares -> correct for any input.

#define NPIX 6400
#define NT   1024
#define NB   4096

// dynamic smem layout (bytes):
//   [0,     16384)  int cursor[4096]   (hist -> running offsets)
//                   reused as u8 kb[6400] after S4
//   [16384, 32776)  int base0[4097] (+pad)
//   [32776, 83976)  u64 scat[6400]     (keys, bucket-ordered)
//                   reused as int ndlist[6400] after S5
//   [83976, 90376)  u8 ndflag[6400]
#define CUR_OFF    0
#define BASE_OFF   16384
#define SCAT_OFF   32776
#define NDFLAG_OFF 83976
#define SMEM_BYTES 90376

__device__ __forceinline__ int bucket_of(unsigned u) {
    unsigned d = u - 0xC0800000u;
    int b = (u < 0xC0800000u) ? 0 : (int)(d >> 9);
    return b > (NB - 1) ? (NB - 1) : b;
}

__global__ void __launch_bounds__(NT, 1)
bb_kernel(const float* __restrict__ x, float* __restrict__ out) {
    extern __shared__ unsigned char smem[];
    int*                cursor = (int*)(smem + CUR_OFF);
    unsigned char*      kb     = smem + CUR_OFF;           // reuse after S4
    int*                base0  = (int*)(smem + BASE_OFF);
    unsigned long long* scat   = (unsigned long long*)(smem + SCAT_OFF);
    int*                ndlist = (int*)(smem + SCAT_OFF);  // reuse after S5
    unsigned char*      ndflag = smem + NDFLAG_OFF;
    __shared__ int wsum[32];
    __shared__ int wcnt[32];
    __shared__ int sG;

    const int tid  = threadIdx.x;
    const int lane = tid & 31;
    const int wid  = tid >> 5;

    // ---- S1: prefetch all of x to L2, zero hist, zero out ----
    if (tid < 1000) {   // 128000 B / 128 B = 1000 lines
        const char* p = (const char*)x + tid * 128;
        asm volatile("prefetch.global.L2 [%0];" :: "l"(p));
    }
    ((int4*)cursor)[tid] = make_int4(0, 0, 0, 0);   // 4096 ints, 4/thread
    float4* o4 = (float4*)out;
    #pragma unroll
    for (int i = tid; i < (NPIX * 5) / 4; i += NT)
        o4[i] = make_float4(0.f, 0.f, 0.f, 0.f);
    __syncthreads();

    // ---- S2: histogram of valid scores ----
    #pragma unroll
    for (int i = tid; i < NPIX; i += NT) {
        float s = x[i];                       // channel 0 (prob)
        if (s > 0.9f)
            atomicAdd(&cursor[bucket_of(~__float_as_uint(s))], 1);
    }
    __syncthreads();

    // ---- S3: exclusive prefix sum over 4096 buckets (int4, 4/thread) ----
    int4 c4 = ((int4*)cursor)[tid];
    int local = c4.x + c4.y + c4.z + c4.w;
    int v = local;
    #pragma unroll
    for (int j = 1; j < 32; j <<= 1) {
        int n = __shfl_up_sync(0xffffffffu, v, j);
        if (lane >= j) v += n;
    }
    if (lane == 31) wsum[wid] = v;
    __syncthreads();
    if (wid == 0) {
        int w = wsum[lane];
        #pragma unroll
        for (int j = 1; j < 32; j <<= 1) {
            int n = __shfl_up_sync(0xffffffffu, w, j);
            if (lane >= j) w += n;
        }
        wsum[lane] = w;
    }
    __syncthreads();
    int ex = v - local + (wid ? wsum[wid - 1] : 0);
    int4 b4 = make_int4(ex, ex + c4.x, ex + c4.x + c4.y,
                        ex + c4.x + c4.y + c4.z);
    ((int4*)base0)[tid]  = b4;
    ((int4*)cursor)[tid] = b4;
    const int M = wsum[31];
    if (tid == 0) base0[NB] = M;
    __syncthreads();

    if (M > 0) {
        // ---- S4: scatter pass (ch0 L1-hot) ----
        #pragma unroll
        for (int i = tid; i < NPIX; i += NT) {
            float s = x[i];
            if (s > 0.9f) {
                unsigned u = ~__float_as_uint(s);
                int slot = atomicAdd(&cursor[bucket_of(u)], 1);
                scat[slot] = (((unsigned long long)u) << 32) | (unsigned)i;
            }
        }
        __syncthreads();   // cursor dead -> kb reuse OK

        // ---- S5: rank + gather + write rows (1/thread typical) ----
        // b5 = (f0, f1, f0+f2, f1+f3, f4); box = (f1, f0+f2, f1+f3, f4)
        for (int p = tid; p < M; p += NT) {
            unsigned long long key = scat[p];
            unsigned u = (unsigned)(key >> 32);
            int b = bucket_of(u);
            int s0 = base0[b], e0 = base0[b + 1];
            int r = s0;
            if (e0 - s0 > 1)
                for (int q = s0; q < e0; q++) r += (scat[q] < key);

            unsigned i = (unsigned)key;
            float f0 = __uint_as_float(~u);
            float f1 = x[NPIX + i];           // L2-warm (prefetched)
            float f2 = x[2 * NPIX + i];
            float f3 = x[3 * NPIX + i];
            float f4 = x[4 * NPIX + i];
            float cc2 = f0 + f2;
            float cc3 = f1 + f3;
            out[r * 5 + 0] = f0;
            out[r * 5 + 1] = f1;
            out[r * 5 + 2] = cc2;
            out[r * 5 + 3] = cc3;
            out[r * 5 + 4] = f4;
            ndflag[r] = ((cc3 - f1) > 0.f && (f4 - cc2) > 0.f) ? 1 : 0;
        }
        __syncthreads();   // scat dead -> ndlist reuse OK

        // ---- S6a: order-preserving non-degenerate list build ----
        int g;
        if (M <= NT) {
            // parallel: warp w handles ranks [32w, 32w+32)
            int r = wid * 32 + lane;
            bool f = (r < M) && (ndflag[r] != 0);
            unsigned mybal = __ballot_sync(0xffffffffu, f);
            if (lane == 0) wcnt[wid] = __popc(mybal);
            __syncthreads();
            if (tid < 32) {
                int c = wcnt[lane];
                int p = c;
                #pragma unroll
                for (int j = 1; j < 32; j <<= 1) {
                    int n = __shfl_up_sync(0xffffffffu, p, j);
                    if (lane >= j) p += n;
                }
                wcnt[lane] = p - c;           // exclusive offsets
                if (lane == 31) sG = p;       // total count
            }
            __syncthreads();
            if (f) ndlist[wcnt[wid] + __popc(mybal & ((1u << lane) - 1u))] = r;
            __syncthreads();
            g = sG;
        } else {
            // fallback (M > 1024; ~never): warp-0 sequential build
            if (tid < 32) {
                int gg = 0;
                for (int base = 0; base < M; base += 32) {
                    int r = base + lane;
                    bool f = (r < M) && (ndflag[r] != 0);
                    unsigned bal = __ballot_sync(0xffffffffu, f);
                    if (f)
                        ndlist[gg + __popc(bal & ((1u << lane) - 1u))] = r;
                    gg += __popc(bal);
                }
                if (lane == 0) sG = gg;
            }
            __syncthreads();
            g = sG;
        }

        // ---- S6b: warp 0 — greedy NMS over non-degenerate boxes ----
        // degenerate boxes (w<=0 or h<=0) have IoU 0 with everything:
        // never suppressed, never suppress -> rows stay as written.
        if (tid < 32) {
            for (int i2 = 0; i2 < g; i2++) {
                int ri = ndlist[i2];
                float ax0 = out[ri * 5 + 1], ay0 = out[ri * 5 + 2];
                float ax1 = out[ri * 5 + 3], ay1 = out[ri * 5 + 4];
                float aarea = fmaxf(ax1 - ax0, 0.f) * fmaxf(ay1 - ay0, 0.f);
                bool sup = false;
                for (int j = lane; j < i2; j += 32) {
                    if (kb[j]) {
                        int rj = ndlist[j];
                        float bx0 = out[rj * 5 + 1], by0 = out[rj * 5 + 2];
                        float bx1 = out[rj * 5 + 3], by1 = out[rj * 5 + 4];
                        float barea = fmaxf(bx1 - bx0, 0.f) *
                                      fmaxf(by1 - by0, 0.f);
                        float iw = fminf(ax1, bx1) - fmaxf(ax0, bx0);
                        float ih = fminf(ay1, by1) - fmaxf(ay0, by0);
                        float inter = fmaxf(iw, 0.f) * fmaxf(ih, 0.f);
                        float uni = aarea + barea - inter;
                        if (inter / fmaxf(uni, 1e-9f) > 0.5f) sup = true;
                    }
                }
                sup = __any_sync(0xffffffffu, sup);
                if (lane == 0) {
                    kb[i2] = sup ? 0 : 1;
                    if (sup) {   // suppressed row -> zeros
                        out[ri * 5 + 0] = 0.f;
                        out[ri * 5 + 1] = 0.f;
                        out[ri * 5 + 2] = 0.f;
                        out[ri * 5 + 3] = 0.f;
                        out[ri * 5 + 4] = 0.f;
                    }
                }
                __syncwarp();
            }
        }
    }
}

extern "C" void kernel_launch(void* const* d_in, const int* in_sizes, int n_in,
                              void* d_out, int out_size) {
    const float* x = (const float*)d_in[0];
    float* out = (float*)d_out;
    cudaFuncSetAttribute(bb_kernel,
                         cudaFuncAttributeMaxDynamicSharedMemorySize,
                         SMEM_BYTES);
    bb_kernel<<<1, NT, SMEM_BYTES>>>(x, out);
}

// round 12
// speedup vs baseline: 1.2178x; 1.0472x over previous
#include <cuda_runtime.h>

// ReduceBoundingBoxes, SINGLE kernel, SINGLE block, bucketed counting sort,
// ONE full-pixel pass (per-warp compact segments; no serial list atomic).
//   S1: prefetch ALL of x to L2, zero hist, zero out
//   S2: pixel pass: histogram + per-warp segment append (ballot+popc)
//   S3: block prefix-sum over 4096 buckets (int4-vectorized)
//   S4: each warp scatters its own segment into bucket order (~20 elems)
//   S5: rank (in-bucket compares only on collisions) + gather + write rows
//   S6: parallel order-preserving non-degenerate list build + warp-0 NMS
// x: (5, 80, 80) f32 channel-major. out: (6400, 5) f32.
//
// key = (u64(~bits(score)) << 32) | idx ; ascending == (score desc, idx asc).
// Valid scores s in (0.9, 1.0) share exponent 126 -> u = ~bits(s) lies in
// (0xC0800000, 0xC099999A); bucket = clamp((u - 0xC0800000) >> 9, 0, 4095)
// is monotone in u. Out-of-range scores clamp into end buckets, resolved by
// exact u64 compares -> correct for any input.

#define NPIX 6400
#define NT   1024
#define NB   4096
#define SEG  224            // max valid pixels per warp: ceil(6400/1024)*32

// dynamic smem layout (bytes):
//   [0,      57344)  u64 klist[32][224]  (per-warp valid-key segments)
//                    reused as int ndlist[6400] after S4
//   [57344,  73728)  int cursor[4096]    (hist -> running offsets)
//                    reused as u8 kb[6400] after S4
//   [73728,  90240)  int base0[4097] (+pad)
//   [90240, 141440)  u64 scat[6400]      (keys, bucket-ordered)
//   [141440,147840)  u8 ndflag[6400]
#define KLIST_OFF  0
#define CUR_OFF    57344
#define BASE_OFF   73728
#define SCAT_OFF   90240
#define NDFLAG_OFF 141440
#define SMEM_BYTES 147840

__device__ __forceinline__ int bucket_of(unsigned u) {
    unsigned d = u - 0xC0800000u;
    int b = (u < 0xC0800000u) ? 0 : (int)(d >> 9);
    return b > (NB - 1) ? (NB - 1) : b;
}

__global__ void __launch_bounds__(NT, 1)
bb_kernel(const float* __restrict__ x, float* __restrict__ out) {
    extern __shared__ unsigned char smem[];
    unsigned long long* klist  = (unsigned long long*)(smem + KLIST_OFF);
    int*                ndlist = (int*)(smem + KLIST_OFF);  // reuse after S4
    int*                cursor = (int*)(smem + CUR_OFF);
    unsigned char*      kb     = smem + CUR_OFF;            // reuse after S4
    int*                base0  = (int*)(smem + BASE_OFF);
    unsigned long long* scat   = (unsigned long long*)(smem + SCAT_OFF);
    unsigned char*      ndflag = smem + NDFLAG_OFF;
    __shared__ int wsum[32];
    __shared__ int wcnt[32];
    __shared__ int sG;

    const int tid  = threadIdx.x;
    const int lane = tid & 31;
    const int wid  = tid >> 5;

    // ---- S1: prefetch all of x to L2, zero hist, zero out ----
    if (tid < 1000) {   // 128000 B / 128 B = 1000 lines
        const char* p = (const char*)x + tid * 128;
        asm volatile("prefetch.global.L2 [%0];" :: "l"(p));
    }
    ((int4*)cursor)[tid] = make_int4(0, 0, 0, 0);   // 4096 ints, 4/thread
    float4* o4 = (float4*)out;
    #pragma unroll
    for (int i = tid; i < (NPIX * 5) / 4; i += NT)
        o4[i] = make_float4(0.f, 0.f, 0.f, 0.f);
    __syncthreads();

    // ---- S2: ONE pixel pass: histogram + per-warp segment append ----
    int mycnt = 0;                            // warp-uniform running count
    #pragma unroll
    for (int it = 0; it < (NPIX + NT - 1) / NT; it++) {
        int i = tid + it * NT;
        bool v = false;
        unsigned u = 0;
        if (i < NPIX) {
            float s = x[i];                   // channel 0 (prob), L2-warm
            if (s > 0.9f) { v = true; u = ~__float_as_uint(s); }
        }
        if (v) atomicAdd(&cursor[bucket_of(u)], 1);
        unsigned bal = __ballot_sync(0xffffffffu, v);
        if (v) {
            int p = mycnt + __popc(bal & ((1u << lane) - 1u));
            klist[wid * SEG + p] =
                (((unsigned long long)u) << 32) | (unsigned)i;
        }
        mycnt += __popc(bal);
    }
    __syncthreads();

    // ---- S3: exclusive prefix sum over 4096 buckets (int4, 4/thread) ----
    int4 c4 = ((int4*)cursor)[tid];
    int local = c4.x + c4.y + c4.z + c4.w;
    int v = local;
    #pragma unroll
    for (int j = 1; j < 32; j <<= 1) {
        int n = __shfl_up_sync(0xffffffffu, v, j);
        if (lane >= j) v += n;
    }
    if (lane == 31) wsum[wid] = v;
    __syncthreads();
    if (wid == 0) {
        int w = wsum[lane];
        #pragma unroll
        for (int j = 1; j < 32; j <<= 1) {
            int n = __shfl_up_sync(0xffffffffu, w, j);
            if (lane >= j) w += n;
        }
        wsum[lane] = w;
    }
    __syncthreads();
    int ex = v - local + (wid ? wsum[wid - 1] : 0);
    int4 b4 = make_int4(ex, ex + c4.x, ex + c4.x + c4.y,
                        ex + c4.x + c4.y + c4.z);
    ((int4*)base0)[tid]  = b4;
    ((int4*)cursor)[tid] = b4;
    const int M = wsum[31];
    if (tid == 0) base0[NB] = M;
    __syncthreads();

    if (M > 0) {
        // ---- S4: each warp scatters its own segment (~20 elems) ----
        for (int p = lane; p < mycnt; p += 32) {
            unsigned long long key = klist[wid * SEG + p];
            int b = bucket_of((unsigned)(key >> 32));
            scat[atomicAdd(&cursor[b], 1)] = key;
        }
        __syncthreads();   // klist/cursor dead -> ndlist/kb reuse OK

        // ---- S5: rank + gather + write rows (1/thread typical) ----
        // b5 = (f0, f1, f0+f2, f1+f3, f4); box = (f1, f0+f2, f1+f3, f4)
        for (int p = tid; p < M; p += NT) {
            unsigned long long key = scat[p];
            unsigned u = (unsigned)(key >> 32);
            int b = bucket_of(u);
            int s0 = base0[b], e0 = base0[b + 1];
            int r = s0;
            if (e0 - s0 > 1)
                for (int q = s0; q < e0; q++) r += (scat[q] < key);

            unsigned i = (unsigned)key;
            float f0 = __uint_as_float(~u);
            float f1 = x[NPIX + i];           // L2-warm (prefetched)
            float f2 = x[2 * NPIX + i];
            float f3 = x[3 * NPIX + i];
            float f4 = x[4 * NPIX + i];
            float cc2 = f0 + f2;
            float cc3 = f1 + f3;
            out[r * 5 + 0] = f0;
            out[r * 5 + 1] = f1;
            out[r * 5 + 2] = cc2;
            out[r * 5 + 3] = cc3;
            out[r * 5 + 4] = f4;
            ndflag[r] = ((cc3 - f1) > 0.f && (f4 - cc2) > 0.f) ? 1 : 0;
        }
        __syncthreads();

        // ---- S6a: order-preserving non-degenerate list build ----
        int g;
        if (M <= NT) {
            int r = wid * 32 + lane;
            bool f = (r < M) && (ndflag[r] != 0);
            unsigned mybal = __ballot_sync(0xffffffffu, f);
            if (lane == 0) wcnt[wid] = __popc(mybal);
            __syncthreads();
            if (tid < 32) {
                int c = wcnt[lane];
                int p = c;
                #pragma unroll
                for (int j = 1; j < 32; j <<= 1) {
                    int n = __shfl_up_sync(0xffffffffu, p, j);
                    if (lane >= j) p += n;
                }
                wcnt[lane] = p - c;           // exclusive offsets
                if (lane == 31) sG = p;       // total count
            }
            __syncthreads();
            if (f) ndlist[wcnt[wid] + __popc(mybal & ((1u << lane) - 1u))] = r;
            __syncthreads();
            g = sG;
        } else {
            // fallback (M > 1024; ~never): warp-0 sequential build
            if (tid < 32) {
                int gg = 0;
                for (int base = 0; base < M; base += 32) {
                    int r = base + lane;
                    bool f = (r < M) && (ndflag[r] != 0);
                    unsigned bal = __ballot_sync(0xffffffffu, f);
                    if (f)
                        ndlist[gg + __popc(bal & ((1u << lane) - 1u))] = r;
                    gg += __popc(bal);
                }
                if (lane == 0) sG = gg;
            }
            __syncthreads();
            g = sG;
        }

        // ---- S6b: warp 0 — greedy NMS over non-degenerate boxes ----
        // degenerate boxes (w<=0 or h<=0) have IoU 0 with everything:
        // never suppressed, never suppress -> rows stay as written.
        if (tid < 32) {
            for (int i2 = 0; i2 < g; i2++) {
                int ri = ndlist[i2];
                float ax0 = out[ri * 5 + 1], ay0 = out[ri * 5 + 2];
                float ax1 = out[ri * 5 + 3], ay1 = out[ri * 5 + 4];
                float aarea = fmaxf(ax1 - ax0, 0.f) * fmaxf(ay1 - ay0, 0.f);
                bool sup = false;
                for (int j = lane; j < i2; j += 32) {
                    if (kb[j]) {
                        int rj = ndlist[j];
                        float bx0 = out[rj * 5 + 1], by0 = out[rj * 5 + 2];
                        float bx1 = out[rj * 5 + 3], by1 = out[rj * 5 + 4];
                        float barea = fmaxf(bx1 - bx0, 0.f) *
                                      fmaxf(by1 - by0, 0.f);
                        float iw = fminf(ax1, bx1) - fmaxf(ax0, bx0);
                        float ih = fminf(ay1, by1) - fmaxf(ay0, by0);
                        float inter = fmaxf(iw, 0.f) * fmaxf(ih, 0.f);
                        float uni = aarea + barea - inter;
                        if (inter / fmaxf(uni, 1e-9f) > 0.5f) sup = true;
                    }
                }
                sup = __any_sync(0xffffffffu, sup);
                if (lane == 0) {
                    kb[i2] = sup ? 0 : 1;
                    if (sup) {   // suppressed row -> zeros
                        out[ri * 5 + 0] = 0.f;
                        out[ri * 5 + 1] = 0.f;
                        out[ri * 5 + 2] = 0.f;
                        out[ri * 5 + 3] = 0.f;
                        out[ri * 5 + 4] = 0.f;
                    }
                }
                __syncwarp();
            }
        }
    }
}

extern "C" void kernel_launch(void* const* d_in, const int* in_sizes, int n_in,
                              void* d_out, int out_size) {
    const float* x = (const float*)d_in[0];
    float* out = (float*)d_out;
    cudaFuncSetAttribute(bb_kernel,
                         cudaFuncAttributeMaxDynamicSharedMemorySize,
                         SMEM_BYTES);
    bb_kernel<<<1, NT, SMEM_BYTES>>>(x, out);
}

// round 13
// speedup vs baseline: 1.3851x; 1.1373x over previous
#include <cuda_runtime.h>

// ReduceBoundingBoxes: ONE kernel, 9 blocks.
//   blocks 1..8 (helpers): zero out (1 float4/thread), block 1 also prefetches
//     x to L2; signal d_zdone and exit.
//   block 0 (worker): float4 pixel pass (hist + per-warp segment append) ->
//     prefix sum -> per-warp scatter -> [spin on zero-done] -> rank+gather+
//     write rows -> parallel nd-list build -> warp-0 greedy NMS.
// x: (5, 80, 80) f32 channel-major. out: (6400, 5) f32.
//
// key = (u64(~bits(score)) << 32) | idx ; ascending == (score desc, idx asc).
// Valid scores s in (0.9, 1.0) share exponent 126 -> u = ~bits(s) lies in
// (0xC0800000, 0xC099999A); bucket = clamp((u - 0xC0800000) >> 9, 0, 4095)
// is monotone in u. Out-of-range scores clamp into end buckets, resolved by
// exact u64 compares -> correct for any input.

#define NPIX 6400
#define NT   1024
#define NB   4096
#define NZB  8              // helper (zeroing) blocks
#define SEG  256            // max valid pixels per warp (2 iters * 128)

__device__ int d_zdone;     // zero-init; block 0 resets at end of each run

// dynamic smem layout (bytes), block 0 only:
//   [0,      65536)  u64 klist[32][256]  (per-warp valid-key segments)
//                    reused as int ndlist[6400] after S4
//   [65536,  81920)  int cursor[4096]    (hist -> running offsets)
//                    reused as u8 kb[6400] after S4
//   [81920,  98432)  int base0[4097] (+pad)
//   [98432, 149632)  u64 scat[6400]      (keys, bucket-ordered)
//   [149632,156032)  u8 ndflag[6400]
#define KLIST_OFF  0
#define CUR_OFF    65536
#define BASE_OFF   81920
#define SCAT_OFF   98432
#define NDFLAG_OFF 149632
#define SMEM_BYTES 156032

__device__ __forceinline__ int bucket_of(unsigned u) {
    unsigned d = u - 0xC0800000u;
    int b = (u < 0xC0800000u) ? 0 : (int)(d >> 9);
    return b > (NB - 1) ? (NB - 1) : b;
}

__global__ void __launch_bounds__(NT, 1)
bb_kernel(const float* __restrict__ x, float* __restrict__ out) {
    const int tid  = threadIdx.x;
    const int lane = tid & 31;
    const int wid  = tid >> 5;

    // ================= helper blocks: zero out + prefetch =================
    if (blockIdx.x != 0) {
        int zb = blockIdx.x - 1;
        if (zb == 0 && tid < 1000) {   // prefetch x: 128000 B = 1000 lines
            const char* p = (const char*)x + tid * 128;
            asm volatile("prefetch.global.L2 [%0];" :: "l"(p));
        }
        int gi = zb * NT + tid;        // 8 * 1024 = 8192 >= 8000 float4
        if (gi < (NPIX * 5) / 4)
            ((float4*)out)[gi] = make_float4(0.f, 0.f, 0.f, 0.f);
        __threadfence();               // release: zeros visible device-wide
        __syncthreads();
        if (tid == 0) atomicAdd(&d_zdone, 1);
        return;
    }

    // ======================== worker block 0 ==============================
    extern __shared__ unsigned char smem[];
    unsigned long long* klist  = (unsigned long long*)(smem + KLIST_OFF);
    int*                ndlist = (int*)(smem + KLIST_OFF);  // reuse after S4
    int*                cursor = (int*)(smem + CUR_OFF);
    unsigned char*      kb     = smem + CUR_OFF;            // reuse after S4
    int*                base0  = (int*)(smem + BASE_OFF);
    unsigned long long* scat   = (unsigned long long*)(smem + SCAT_OFF);
    unsigned char*      ndflag = smem + NDFLAG_OFF;
    __shared__ int wsum[32];
    __shared__ int wcnt[32];
    __shared__ int sG;

    // ---- S1: zero histogram ----
    ((int4*)cursor)[tid] = make_int4(0, 0, 0, 0);   // 4096 ints, 4/thread
    __syncthreads();

    // ---- S2: float4 pixel pass: hist + per-warp segment append ----
    int mycnt = 0;                     // warp-uniform running segment count
    #pragma unroll
    for (int it = 0; it < 2; it++) {
        int i4 = tid + it * NT;        // 1600 float4 cover 6400 pixels
        float4 s4 = make_float4(0.f, 0.f, 0.f, 0.f);
        if (i4 < NPIX / 4) s4 = ((const float4*)x)[i4];
        unsigned uu[4];
        int vm = 0, cnt = 0;
        float sv[4] = {s4.x, s4.y, s4.z, s4.w};
        #pragma unroll
        for (int e = 0; e < 4; e++) {
            if (sv[e] > 0.9f) {
                uu[e] = ~__float_as_uint(sv[e]);
                vm |= 1 << e;
                cnt++;
                atomicAdd(&cursor[bucket_of(uu[e])], 1);
            }
        }
        // warp inclusive scan of cnt
        int inc = cnt;
        #pragma unroll
        for (int j = 1; j < 32; j <<= 1) {
            int n = __shfl_up_sync(0xffffffffu, inc, j);
            if (lane >= j) inc += n;
        }
        int base = mycnt + inc - cnt;
        int k = 0;
        #pragma unroll
        for (int e = 0; e < 4; e++) {
            if (vm & (1 << e)) {
                klist[wid * SEG + base + k] =
                    (((unsigned long long)uu[e]) << 32) |
                    (unsigned)(i4 * 4 + e);
                k++;
            }
        }
        mycnt += __shfl_sync(0xffffffffu, inc, 31);
    }
    __syncthreads();

    // ---- S3: exclusive prefix sum over 4096 buckets (int4, 4/thread) ----
    int4 c4 = ((int4*)cursor)[tid];
    int local = c4.x + c4.y + c4.z + c4.w;
    int v = local;
    #pragma unroll
    for (int j = 1; j < 32; j <<= 1) {
        int n = __shfl_up_sync(0xffffffffu, v, j);
        if (lane >= j) v += n;
    }
    if (lane == 31) wsum[wid] = v;
    __syncthreads();
    if (wid == 0) {
        int w = wsum[lane];
        #pragma unroll
        for (int j = 1; j < 32; j <<= 1) {
            int n = __shfl_up_sync(0xffffffffu, w, j);
            if (lane >= j) w += n;
        }
        wsum[lane] = w;
    }
    __syncthreads();
    int ex = v - local + (wid ? wsum[wid - 1] : 0);
    int4 b4 = make_int4(ex, ex + c4.x, ex + c4.x + c4.y,
                        ex + c4.x + c4.y + c4.z);
    ((int4*)base0)[tid]  = b4;
    ((int4*)cursor)[tid] = b4;
    const int M = wsum[31];
    if (tid == 0) base0[NB] = M;
    __syncthreads();

    if (M > 0) {
        // ---- S4: each warp scatters its own segment (~20 elems) ----
        for (int p = lane; p < mycnt; p += 32) {
            unsigned long long key = klist[wid * SEG + p];
            int b = bucket_of((unsigned)(key >> 32));
            scat[atomicAdd(&cursor[b], 1)] = key;
        }
        __syncthreads();   // klist/cursor dead -> ndlist/kb reuse OK

        // ---- spin: wait for helper blocks' zeros before writing rows ----
        if (tid == 0)
            while (atomicAdd(&d_zdone, 0) < NZB) { }
        __syncthreads();
        __threadfence();   // acquire

        // ---- S5: rank + gather + write rows (1/thread typical) ----
        // b5 = (f0, f1, f0+f2, f1+f3, f4); box = (f1, f0+f2, f1+f3, f4)
        for (int p = tid; p < M; p += NT) {
            unsigned long long key = scat[p];
            unsigned u = (unsigned)(key >> 32);
            int b = bucket_of(u);
            int s0 = base0[b], e0 = base0[b + 1];
            int r = s0;
            if (e0 - s0 > 1)
                for (int q = s0; q < e0; q++) r += (scat[q] < key);

            unsigned i = (unsigned)key;
            float f0 = __uint_as_float(~u);
            float f1 = x[NPIX + i];           // L2-warm (prefetched)
            float f2 = x[2 * NPIX + i];
            float f3 = x[3 * NPIX + i];
            float f4 = x[4 * NPIX + i];
            float cc2 = f0 + f2;
            float cc3 = f1 + f3;
            out[r * 5 + 0] = f0;
            out[r * 5 + 1] = f1;
            out[r * 5 + 2] = cc2;
            out[r * 5 + 3] = cc3;
            out[r * 5 + 4] = f4;
            ndflag[r] = ((cc3 - f1) > 0.f && (f4 - cc2) > 0.f) ? 1 : 0;
        }
        __syncthreads();

        // ---- S6a: order-preserving non-degenerate list build ----
        int g;
        if (M <= NT) {
            int r = wid * 32 + lane;
            bool f = (r < M) && (ndflag[r] != 0);
            unsigned mybal = __ballot_sync(0xffffffffu, f);
            if (lane == 0) wcnt[wid] = __popc(mybal);
            __syncthreads();
            if (tid < 32) {
                int c = wcnt[lane];
                int p = c;
                #pragma unroll
                for (int j = 1; j < 32; j <<= 1) {
                    int n = __shfl_up_sync(0xffffffffu, p, j);
                    if (lane >= j) p += n;
                }
                wcnt[lane] = p - c;           // exclusive offsets
                if (lane == 31) sG = p;
            }
            __syncthreads();
            if (f) ndlist[wcnt[wid] + __popc(mybal & ((1u << lane) - 1u))] = r;
            __syncthreads();
            g = sG;
        } else {
            // fallback (M > 1024; ~never): warp-0 sequential build
            if (tid < 32) {
                int gg = 0;
                for (int base = 0; base < M; base += 32) {
                    int r = base + lane;
                    bool f = (r < M) && (ndflag[r] != 0);
                    unsigned bal = __ballot_sync(0xffffffffu, f);
                    if (f)
                        ndlist[gg + __popc(bal & ((1u << lane) - 1u))] = r;
                    gg += __popc(bal);
                }
                if (lane == 0) sG = gg;
            }
            __syncthreads();
            g = sG;
        }

        // ---- S6b: warp 0 — greedy NMS over non-degenerate boxes ----
        // degenerate boxes (w<=0 or h<=0) have IoU 0 with everything:
        // never suppressed, never suppress -> rows stay as written.
        if (tid < 32) {
            for (int i2 = 0; i2 < g; i2++) {
                int ri = ndlist[i2];
                float ax0 = out[ri * 5 + 1], ay0 = out[ri * 5 + 2];
                float ax1 = out[ri * 5 + 3], ay1 = out[ri * 5 + 4];
                float aarea = fmaxf(ax1 - ax0, 0.f) * fmaxf(ay1 - ay0, 0.f);
                bool sup = false;
                for (int j = lane; j < i2; j += 32) {
                    if (kb[j]) {
                        int rj = ndlist[j];
                        float bx0 = out[rj * 5 + 1], by0 = out[rj * 5 + 2];
                        float bx1 = out[rj * 5 + 3], by1 = out[rj * 5 + 4];
                        float barea = fmaxf(bx1 - bx0, 0.f) *
                                      fmaxf(by1 - by0, 0.f);
                        float iw = fminf(ax1, bx1) - fmaxf(ax0, bx0);
                        float ih = fminf(ay1, by1) - fmaxf(ay0, by0);
                        float inter = fmaxf(iw, 0.f) * fmaxf(ih, 0.f);
                        float uni = aarea + barea - inter;
                        if (inter / fmaxf(uni, 1e-9f) > 0.5f) sup = true;
                    }
                }
                sup = __any_sync(0xffffffffu, sup);
                if (lane == 0) {
                    kb[i2] = sup ? 0 : 1;
                    if (sup) {   // suppressed row -> zeros
                        out[ri * 5 + 0] = 0.f;
                        out[ri * 5 + 1] = 0.f;
                        out[ri * 5 + 2] = 0.f;
                        out[ri * 5 + 3] = 0.f;
                        out[ri * 5 + 4] = 0.f;
                    }
                }
                __syncwarp();
            }
        }
    } else {
        // still must consume the helper signal deterministically
        if (tid == 0)
            while (atomicAdd(&d_zdone, 0) < NZB) { }
        __syncthreads();
    }

    // ---- reset flag for next graph replay ----
    __syncthreads();
    if (tid == 0) d_zdone = 0;
}

extern "C" void kernel_launch(void* const* d_in, const int* in_sizes, int n_in,
                              void* d_out, int out_size) {
    const float* x = (const float*)d_in[0];
    float* out = (float*)d_out;
    cudaFuncSetAttribute(bb_kernel,
                         cudaFuncAttributeMaxDynamicSharedMemorySize,
                         SMEM_BYTES);
    bb_kernel<<<NZB + 1, NT, SMEM_BYTES>>>(x, out);
}